// round 2
// baseline (speedup 1.0000x reference)
#include <cuda_runtime.h>
#include <math.h>

// ---------------------------------------------------------------------------
// ChebConv2D  (B=32, C=64, H=W=128, O=64, K=9)
//
// Restructured pipeline (mathematically identical to reference):
//   ch[b,c,kh,kw] = sum_h Tp[kh,h] * sum_w x[b,c,h,w] * Tp[kw,w]
//   mm[b,o,kh,kw] = sum_c ch[b,c,kh,kw] * W_w[c,o,kw]
//   e [b,f,kh,kw] = sum_o mm[b,o,kh,kw] * W_h[o,f,kh]
//   out[b,f,h,w]  = sum_kh Te[h,kh] * sum_kw e[b,f,kh,kw] * Te[w,kw]
// ---------------------------------------------------------------------------

#define BB   32
#define CC   64
#define HH   128
#define WW   128
#define OO   64
#define KK   9
#define KK2  81          // 9*9
#define BC   (BB*CC)     // 2048
#define BF   (BB*OO)     // 2048
#define IMG  (HH*WW)     // 16384

// Scratch (no allocations allowed)
__device__ float g_Tp[KK*HH];        // Tp[k][i] at k*128+i   (pinv rows)
__device__ float g_Te[HH*KK];        // Te[i][k] at i*9+k
__device__ float g_ch[BC*KK2];       // [b][c][kh][kw]
__device__ float g_mm[BF*KK2];       // [b][o][kh][kw]
__device__ float g_e [BF*KK2];       // [b][f][kh][kw]

// ---------------------------------------------------------------------------
// Setup: Chebyshev matrices. T built in float32 (to match numpy's float32 T),
// pinv via fp64 normal equations + Gauss-Jordan (T well-conditioned).
// ---------------------------------------------------------------------------
__global__ void k_setup() {
    __shared__ double Td[HH*KK];
    __shared__ double Gm[KK][19];     // augmented [G | I]
    int i = threadIdx.x;              // 128 threads

    {
        double xd = (double)i / 127.0;
        float  xf = (float)xd;
        float  xn = 2.0f * xf - 1.0f;
        xn = fminf(fmaxf(xn, -1.0f + 1e-6f), 1.0f - 1e-6f);
        double th = acos((double)xn);
        #pragma unroll
        for (int k = 0; k < KK; k++) {
            float tv = (float)cos(th * (double)k);
            g_Te[i*KK + k] = tv;
            Td[i*KK + k]   = (double)tv;
        }
    }
    __syncthreads();

    if (i < KK2) {
        int a = i / KK, b = i % KK;
        double s = 0.0;
        for (int j = 0; j < HH; j++) s += Td[j*KK + a] * Td[j*KK + b];
        Gm[a][b]     = s;
        Gm[a][9 + b] = (a == b) ? 1.0 : 0.0;
    }
    __syncthreads();

    if (i == 0) {
        // Gauss-Jordan (G is SPD, no pivoting needed)
        for (int p = 0; p < KK; p++) {
            double inv = 1.0 / Gm[p][p];
            for (int c = 0; c < 18; c++) Gm[p][c] *= inv;
            for (int r = 0; r < KK; r++) {
                if (r == p) continue;
                double f = Gm[r][p];
                for (int c = 0; c < 18; c++) Gm[r][c] -= f * Gm[p][c];
            }
        }
    }
    __syncthreads();

    // Tp[k][j] = sum_a Ginv[k][a] * T[j][a]
    for (int t = i; t < KK*HH; t += 128) {
        int k = t >> 7, j = t & 127;
        double s = 0.0;
        #pragma unroll
        for (int a = 0; a < KK; a++) s += Gm[k][9 + a] * Td[j*KK + a];
        g_Tp[t] = (float)s;
    }
}

// ---------------------------------------------------------------------------
// K1: per (b,c) image -> ch[b,c,kh,kw]  (dual-axis analysis, fused)
// 128 threads, thread = h-row. x streamed through smem in two w-halves.
// ---------------------------------------------------------------------------
__global__ __launch_bounds__(128) void k1_analysis(const float* __restrict__ x) {
    __shared__ float xs[HH * 68];     // [128 h][64 w + pad4]  (34.8 KB)
    __shared__ float tps[KK * 132];   // padded Tp rows
    __shared__ float cs[HH * 12];     // per-h width coefficients

    int tid = threadIdx.x;            // 128
    int bc  = blockIdx.x;             // 2048
    const float* xg = x + (size_t)bc * IMG;

    for (int i = tid; i < KK*HH; i += 128)
        tps[(i >> 7)*132 + (i & 127)] = g_Tp[i];

    float acc[KK];
    #pragma unroll
    for (int k = 0; k < KK; k++) acc[k] = 0.0f;

    for (int half = 0; half < 2; half++) {
        // stage 64-wide slab: coalesced float4 LDG + conflict-free STS.128
        for (int i = tid; i < 2048; i += 128) {
            int h = i >> 4, w4 = (i & 15) << 2;
            *(float4*)(xs + h*68 + w4) =
                *(const float4*)(xg + h*WW + half*64 + w4);
        }
        __syncthreads();

        const float4* xr = (const float4*)(xs + tid*68);
        #pragma unroll 4
        for (int cw = 0; cw < 16; cw++) {
            float4 xv = xr[cw];
            int woff = half*64 + cw*4;
            #pragma unroll
            for (int k = 0; k < KK; k++) {
                float4 tv = *(const float4*)(tps + k*132 + woff);
                acc[k] += xv.x*tv.x + xv.y*tv.y + xv.z*tv.z + xv.w*tv.w;
            }
        }
        __syncthreads();
    }

    // stash per-row width coefficients
    #pragma unroll
    for (int k = 0; k < KK; k++) cs[tid*12 + k] = acc[k];
    __syncthreads();

    // height analysis within the block (81 outputs)
    if (tid < KK2) {
        int kh = tid / KK, kw = tid % KK;
        float s = 0.0f;
        #pragma unroll 8
        for (int h = 0; h < HH; h++)
            s += tps[kh*132 + h] * cs[h*12 + kw];
        g_ch[(size_t)bc * KK2 + tid] = s;
    }
}

// ---------------------------------------------------------------------------
// K3a: width channel mix   mm[b,o,j] = sum_c ch[b,c,j] * W_w[c,o,kw]
// grid: 32 b x 8 o-tiles of 8
// ---------------------------------------------------------------------------
__global__ __launch_bounds__(128) void k3a_mixw(const float* __restrict__ Ww) {
    __shared__ float chs[CC * KK2];   // 5184 floats
    __shared__ float Ws[CC * 72];     // 4608 floats
    int tid = threadIdx.x;
    int b   = blockIdx.x >> 3;
    int o0  = (blockIdx.x & 7) * 8;

    for (int i = tid; i < CC*KK2; i += 128)
        chs[i] = g_ch[(size_t)b * CC * KK2 + i];
    for (int i = tid; i < CC*72; i += 128) {
        int c = i / 72, r = i % 72;
        Ws[i] = Ww[(c*OO + o0)*KK + r];
    }
    __syncthreads();

    for (int i = tid; i < 8*KK2; i += 128) {
        int oo = i / KK2, j = i % KK2, kw = j % KK;
        float s = 0.0f;
        #pragma unroll 8
        for (int c = 0; c < CC; c++)
            s += chs[c*KK2 + j] * Ws[c*72 + oo*KK + kw];
        g_mm[(size_t)(b*OO + o0 + oo) * KK2 + j] = s;
    }
}

// ---------------------------------------------------------------------------
// K3b: height channel mix  e[b,f,j] = sum_o mm[b,o,j] * W_h[o,f,kh]
// ---------------------------------------------------------------------------
__global__ __launch_bounds__(128) void k3b_mixh(const float* __restrict__ Wh) {
    __shared__ float mms[OO * KK2];
    __shared__ float Ws[OO * 72];
    int tid = threadIdx.x;
    int b   = blockIdx.x >> 3;
    int f0  = (blockIdx.x & 7) * 8;

    for (int i = tid; i < OO*KK2; i += 128)
        mms[i] = g_mm[(size_t)b * OO * KK2 + i];
    for (int i = tid; i < OO*72; i += 128) {
        int o = i / 72, r = i % 72;
        Ws[i] = Wh[(o*OO + f0)*KK + r];
    }
    __syncthreads();

    for (int i = tid; i < 8*KK2; i += 128) {
        int ff = i / KK2, j = i % KK2, kh = j / KK;
        float s = 0.0f;
        #pragma unroll 8
        for (int o = 0; o < OO; o++)
            s += mms[o*KK2 + j] * Ws[o*72 + ff*KK + kh];
        g_e[(size_t)(b*OO + f0 + ff) * KK2 + j] = s;
    }
}

// ---------------------------------------------------------------------------
// K4: dual-axis synthesis  out[b,f,h,w] = sum_kh Te[h,kh] * v[w][kh],
//     v[w][kh] = sum_kw e[kh,kw] * Te[w,kw]
// one block per (b,f); 256 threads; thread = (w, h-half)
// ---------------------------------------------------------------------------
__global__ __launch_bounds__(256) void k4_synth(float* __restrict__ out) {
    __shared__ float es[KK2];
    __shared__ float tes[HH*KK];
    __shared__ float vs[WW*KK];
    int tid = threadIdx.x;            // 256
    int bf  = blockIdx.x;             // 2048

    if (tid < KK2) es[tid] = g_e[(size_t)bf * KK2 + tid];
    for (int i = tid; i < HH*KK; i += 256) tes[i] = g_Te[i];
    __syncthreads();

    // v[w][kh]
    for (int i = tid; i < WW*KK; i += 256) {
        int w = i / KK, kh = i - w*KK;
        float s = 0.0f;
        #pragma unroll
        for (int kw = 0; kw < KK; kw++)
            s += es[kh*KK + kw] * tes[w*KK + kw];
        vs[i] = s;
    }
    __syncthreads();

    int w  = tid & 127;
    int h0 = (tid >> 7) * 64;
    float vr[KK];
    #pragma unroll
    for (int k = 0; k < KK; k++) vr[k] = vs[w*KK + k];

    float* op = out + (size_t)bf * IMG;
    #pragma unroll 4
    for (int h = h0; h < h0 + 64; h++) {
        float s = 0.0f;
        #pragma unroll
        for (int k = 0; k < KK; k++) s += tes[h*KK + k] * vr[k];
        op[h*WW + w] = s;
    }
}

// ---------------------------------------------------------------------------
extern "C" void kernel_launch(void* const* d_in, const int* in_sizes, int n_in,
                              void* d_out, int out_size) {
    const float* x  = (const float*)d_in[0];
    const float* Ww = (const float*)d_in[1];
    const float* Wh = (const float*)d_in[2];
    float* out = (float*)d_out;

    k_setup<<<1, 128>>>();
    k1_analysis<<<BC, 128>>>(x);
    k3a_mixw<<<BB*8, 128>>>(Ww);
    k3b_mixh<<<BB*8, 128>>>(Wh);
    k4_synth<<<BF, 256>>>(out);
}

// round 3
// speedup vs baseline: 3.0229x; 3.0229x over previous
#include <cuda_runtime.h>
#include <math.h>

// ---------------------------------------------------------------------------
// ChebConv2D  (B=32, C=64, H=W=128, O=64, K=9)
//
//   ch[b,c,kh,kw] = sum_h Tp[kh,h] * sum_w x[b,c,h,w] * Tp[kw,w]
//   Wc[kh,kw,c,f] = sum_o W_w[c,o,kw] * W_h[o,f,kh]        (weights only)
//   e [b,f,kh,kw] = sum_c ch[b,c,kh,kw] * Wc[kh,kw,c,f]
//   out[b,f,h,w]  = sum_kh Te[h,kh] * sum_kw e[b,f,kh,kw] * Te[w,kw]
// ---------------------------------------------------------------------------

#define BB   32
#define CC   64
#define HH   128
#define WW   128
#define OO   64
#define KK   9
#define KK2  81
#define BC   (BB*CC)     // 2048
#define BF   (BB*OO)     // 2048
#define IMG  (HH*WW)     // 16384

__device__ float g_Tp[KK*HH];        // Tp[k][i]  (pinv rows), k*128+i
__device__ float g_Te[HH*KK];        // Te[i][k],  i*9+k
__device__ float g_ch[KK2*BC];       // [j][b*64+c]
__device__ float g_wc[KK2*CC*OO];    // [j][c][f]
__device__ float g_e [BF*KK2];       // [b*64+f][j]

// ---------------------------------------------------------------------------
// kA: block 0 = Chebyshev setup (recurrence, no transcendentals; parallel GJ)
//     blocks 1..81 = combined weight Wc[j][c][f]
// ---------------------------------------------------------------------------
__global__ __launch_bounds__(256) void kA_setup_wc(const float* __restrict__ Ww,
                                                   const float* __restrict__ Wh) {
    int tid = threadIdx.x;

    if (blockIdx.x == 0) {
        // ---------------- Chebyshev setup ----------------
        __shared__ double Td[HH*KK];      // T[i][k]
        __shared__ double Gm[KK][19];     // augmented [G | I]
        __shared__ double piv;
        __shared__ double fac[KK];

        if (tid < HH) {
            double xd = (double)tid / 127.0;
            float  xf = (float)xd;
            float  xn = 2.0f * xf - 1.0f;
            xn = fminf(fmaxf(xn, -1.0f + 1e-6f), 1.0f - 1e-6f);
            double x2 = (double)xn;
            double t0 = 1.0, t1 = x2;
            Td[tid*KK + 0] = t0;  g_Te[tid*KK + 0] = 1.0f;
            Td[tid*KK + 1] = t1;  g_Te[tid*KK + 1] = (float)t1;
            #pragma unroll
            for (int k = 2; k < KK; k++) {
                double t2 = 2.0 * x2 * t1 - t0;
                Td[tid*KK + k] = t2;
                g_Te[tid*KK + k] = (float)t2;
                t0 = t1; t1 = t2;
            }
        }
        __syncthreads();

        if (tid < KK2) {
            int a = tid / KK, b = tid % KK;
            double s = 0.0;
            for (int j = 0; j < HH; j++) s += Td[j*KK + a] * Td[j*KK + b];
            Gm[a][b]     = s;
            Gm[a][9 + b] = (a == b) ? 1.0 : 0.0;
        }
        __syncthreads();

        // parallel Gauss-Jordan (G SPD, no pivoting)
        for (int p = 0; p < KK; p++) {
            if (tid == 0) piv = 1.0 / Gm[p][p];
            __syncthreads();
            if (tid < 18) Gm[p][tid] *= piv;
            __syncthreads();
            if (tid < KK) fac[tid] = Gm[tid][p];
            __syncthreads();
            if (tid < 162) {
                int r = tid / 18, c = tid % 18;
                if (r != p) Gm[r][c] -= fac[r] * Gm[p][c];
            }
            __syncthreads();
        }

        // Tp[k][j] = sum_a Ginv[k][a] * T[j][a]
        for (int t = tid; t < KK*HH; t += 256) {
            int k = t >> 7, j = t & 127;
            double s = 0.0;
            #pragma unroll
            for (int a = 0; a < KK; a++) s += Gm[k][9 + a] * Td[j*KK + a];
            g_Tp[t] = (float)s;
        }
    } else {
        // ---------------- Wc[j][c][f] = sum_o Ww[c,o,kw]*Wh[o,f,kh] --------
        __shared__ float sww[CC*(OO+1)];   // [c][o] padded
        __shared__ float swh[OO*OO];       // [o][f]
        int j  = blockIdx.x - 1;           // 0..80
        int kh = j / KK, kw = j % KK;

        for (int i = tid; i < CC*OO; i += 256) {
            int c = i >> 6, o = i & 63;
            sww[c*(OO+1) + o] = Ww[(c*OO + o)*KK + kw];
            swh[i]            = Wh[i*KK + kh];       // i = o*64+f
        }
        __syncthreads();

        int f  = tid & 63;
        int c0 = (tid >> 6) * 16;
        float acc[16];
        #pragma unroll
        for (int i = 0; i < 16; i++) acc[i] = 0.0f;
        for (int o = 0; o < OO; o++) {
            float wh = swh[o*OO + f];
            #pragma unroll
            for (int i = 0; i < 16; i++)
                acc[i] += sww[(c0 + i)*(OO+1) + o] * wh;
        }
        float* wcj = g_wc + (size_t)j * CC * OO;
        #pragma unroll
        for (int i = 0; i < 16; i++)
            wcj[(c0 + i)*OO + f] = acc[i];
    }
}

// ---------------------------------------------------------------------------
// K1: per (b,c) image -> ch[j][bc]. Column-streaming, no x staging.
// 128 threads; thread = w column. h-analysis in registers, then w-analysis.
// ---------------------------------------------------------------------------
__global__ __launch_bounds__(128) void k1_analysis(const float* __restrict__ x) {
    __shared__ float tps[KK*132];     // Tp[k][i], row pad 132 (16B-aligned rows)
    __shared__ float cs[HH*12];       // per-w height coefficients

    int tid = threadIdx.x;            // 128
    int bc  = blockIdx.x;             // 2048
    const float* xg = x + (size_t)bc * IMG + tid;   // column tid

    for (int i = tid; i < KK*HH; i += 128)
        tps[(i >> 7)*132 + (i & 127)] = g_Tp[i];
    __syncthreads();

    float acc[KK];
    #pragma unroll
    for (int k = 0; k < KK; k++) acc[k] = 0.0f;

    #pragma unroll 2
    for (int h4 = 0; h4 < HH; h4 += 4) {
        float x0 = xg[(h4+0)*WW];
        float x1 = xg[(h4+1)*WW];
        float x2 = xg[(h4+2)*WW];
        float x3 = xg[(h4+3)*WW];
        #pragma unroll
        for (int k = 0; k < KK; k++) {
            float4 tv = *(const float4*)(tps + k*132 + h4);   // broadcast
            acc[k] += tv.x*x0 + tv.y*x1 + tv.z*x2 + tv.w*x3;
        }
    }

    #pragma unroll
    for (int k = 0; k < KK; k++) cs[tid*12 + k] = acc[k];
    __syncthreads();

    // width analysis: ch[kh][kw] = sum_w cs[w][kh] * Tp[kw][w]
    if (tid < KK2) {
        int kh = tid / KK, kw = tid % KK;
        float s0 = 0.f, s1 = 0.f, s2 = 0.f, s3 = 0.f;
        #pragma unroll 4
        for (int w = 0; w < HH; w += 4) {
            s0 += cs[(w+0)*12 + kh] * tps[kw*132 + w+0];
            s1 += cs[(w+1)*12 + kh] * tps[kw*132 + w+1];
            s2 += cs[(w+2)*12 + kh] * tps[kw*132 + w+2];
            s3 += cs[(w+3)*12 + kh] * tps[kw*132 + w+3];
        }
        g_ch[(size_t)tid * BC + bc] = (s0+s1) + (s2+s3);
    }
}

// ---------------------------------------------------------------------------
// K2: e[b,f,j] = sum_c ch[j][b,c] * Wc[j][c][f].  One block per j.
// ---------------------------------------------------------------------------
__global__ __launch_bounds__(256) void k2_mix() {
    __shared__ float chs[BB*CC/32];       // not used; replaced below
    (void)chs;
}

__global__ __launch_bounds__(256) void k2_mix_real() {
    __shared__ float ch_s[BB*CC > 2048 ? 1 : 1];
    (void)ch_s;
}

// (real mix kernel)
__global__ __launch_bounds__(256) void k_mix() {
    __shared__ float chs[BB*64];          // [b][c] 8KB
    __shared__ float wcs[CC*OO];          // [c][f] 16KB
    int tid = threadIdx.x;
    int j   = blockIdx.x;                 // 0..80

    for (int i = tid; i < BB*CC; i += 256)
        chs[i] = g_ch[(size_t)j * BC + i];
    for (int i = tid; i < CC*OO; i += 256)
        wcs[i] = g_wc[(size_t)j * CC * OO + i];
    __syncthreads();

    int f  = tid & 63;
    int b0 = (tid >> 6) * 8;
    float acc[8];
    #pragma unroll
    for (int i = 0; i < 8; i++) acc[i] = 0.0f;
    for (int c = 0; c < CC; c++) {
        float wv = wcs[c*OO + f];
        #pragma unroll
        for (int i = 0; i < 8; i++)
            acc[i] += chs[(b0 + i)*CC + c] * wv;
    }
    #pragma unroll
    for (int i = 0; i < 8; i++)
        g_e[(size_t)((b0 + i)*OO + f) * KK2 + j] = acc[i];
}

// ---------------------------------------------------------------------------
// K4: out[b,f,h,w] = sum_kh Te[h,kh] * v[w][kh],
//     v[w][kh] = sum_kw e[kh,kw] * Te[w,kw]
// one block per (b,f); 256 threads; thread = (4 w's, 16 h's); float4 stores
// ---------------------------------------------------------------------------
__global__ __launch_bounds__(256) void k4_synth(float* __restrict__ out) {
    __shared__ float es[KK2];
    __shared__ float tes[HH*KK];
    __shared__ float vs[WW*KK];
    int tid = threadIdx.x;            // 256
    int bf  = blockIdx.x;             // 2048

    if (tid < KK2) es[tid] = g_e[(size_t)bf * KK2 + tid];
    for (int i = tid; i < HH*KK; i += 256) tes[i] = g_Te[i];
    __syncthreads();

    for (int i = tid; i < WW*KK; i += 256) {
        int w = i / KK, kh = i - w*KK;
        float s = 0.0f;
        #pragma unroll
        for (int kw = 0; kw < KK; kw++)
            s += es[kh*KK + kw] * tes[w*KK + kw];
        vs[i] = s;
    }
    __syncthreads();

    int w4 = (tid & 31) * 4;
    int h0 = (tid >> 5) * 16;
    float vr[4][KK];
    #pragma unroll
    for (int i = 0; i < 4; i++)
        #pragma unroll
        for (int k = 0; k < KK; k++) vr[i][k] = vs[(w4 + i)*KK + k];

    float* op = out + (size_t)bf * IMG;
    #pragma unroll 2
    for (int hh = 0; hh < 16; hh++) {
        int h = h0 + hh;
        float t[KK];
        #pragma unroll
        for (int k = 0; k < KK; k++) t[k] = tes[h*KK + k];   // broadcast
        float4 o;
        o.x = 0.f; o.y = 0.f; o.z = 0.f; o.w = 0.f;
        #pragma unroll
        for (int k = 0; k < KK; k++) {
            o.x += t[k] * vr[0][k];
            o.y += t[k] * vr[1][k];
            o.z += t[k] * vr[2][k];
            o.w += t[k] * vr[3][k];
        }
        *(float4*)(op + h*WW + w4) = o;
    }
}

// ---------------------------------------------------------------------------
extern "C" void kernel_launch(void* const* d_in, const int* in_sizes, int n_in,
                              void* d_out, int out_size) {
    const float* x  = (const float*)d_in[0];
    const float* Ww = (const float*)d_in[1];
    const float* Wh = (const float*)d_in[2];
    float* out = (float*)d_out;

    kA_setup_wc<<<1 + KK2, 256>>>(Ww, Wh);
    k1_analysis<<<BC, 128>>>(x);
    k_mix<<<KK2, 256>>>();
    k4_synth<<<BF, 256>>>(out);
}

// round 5
// speedup vs baseline: 3.9179x; 1.2961x over previous
#include <cuda_runtime.h>
#include <math.h>

// ---------------------------------------------------------------------------
// ChebConv2D  (B=32, C=64, H=W=128, O=64, K=9)
//
//   M [b,c,a,bb]  = sum_h sum_w T[h,a] x[b,c,h,w] T[w,bb]       (k1, recurrence)
//   ch[b,c,kh,kw] = Ginv M Ginv^T                               (k1 tail)
//   Wc[kh,kw,c,f] = sum_o W_w[c,o,kw] * W_h[o,f,kh]             (setup)
//   e [b,f,kh,kw] = sum_c ch[b,c,kh,kw] * Wc[kh,kw,c,f]         (k_mix)
//   out[b,f,h,w]  = sum_kh T[h,kh] * sum_kw e[kh,kw] * T[w,kw]  (k4, recurrence)
// ---------------------------------------------------------------------------

#define BB   32
#define CC   64
#define HH   128
#define WW   128
#define OO   64
#define KK   9
#define KK2  81
#define BC   (BB*CC)     // 2048
#define BF   (BB*OO)     // 2048
#define IMG  (HH*WW)     // 16384

__device__ float g_Te[HH*KK];        // T[i][k], i*9+k  (width-analysis tail)
__device__ float g_Gi[KK2];          // Ginv[kh][a]
__device__ float g_xn[HH];           // clamped chebyshev abscissae
__device__ float g_ch[KK2*BC];       // [j][b*64+c]
__device__ float g_wc[KK2*CC*OO];    // [j][c][f]
__device__ float g_e [BF*KK2];       // [b*64+f][j]

// ---------------------------------------------------------------------------
// kA: block 0 = Chebyshev setup; blocks 1..81 = combined weight Wc[j][c][f]
// ---------------------------------------------------------------------------
__global__ __launch_bounds__(256) void kA_setup_wc(const float* __restrict__ Ww,
                                                   const float* __restrict__ Wh) {
    int tid = threadIdx.x;

    if (blockIdx.x == 0) {
        __shared__ double Td[HH*KK];      // T[i][k]
        __shared__ double Gm[KK][19];     // augmented [G | I]
        __shared__ double piv;
        __shared__ double fac[KK];

        if (tid < HH) {
            double xd = (double)tid / 127.0;
            float  xf = (float)xd;
            float  xn = 2.0f * xf - 1.0f;
            xn = fminf(fmaxf(xn, -1.0f + 1e-6f), 1.0f - 1e-6f);
            g_xn[tid] = xn;
            double x2 = (double)xn;
            double t0 = 1.0, t1 = x2;
            Td[tid*KK + 0] = t0;  g_Te[tid*KK + 0] = 1.0f;
            Td[tid*KK + 1] = t1;  g_Te[tid*KK + 1] = (float)t1;
            #pragma unroll
            for (int k = 2; k < KK; k++) {
                double t2 = 2.0 * x2 * t1 - t0;
                Td[tid*KK + k] = t2;
                g_Te[tid*KK + k] = (float)t2;
                t0 = t1; t1 = t2;
            }
        }
        __syncthreads();

        if (tid < KK2) {
            int a = tid / KK, b = tid % KK;
            double s = 0.0;
            for (int j = 0; j < HH; j++) s += Td[j*KK + a] * Td[j*KK + b];
            Gm[a][b]     = s;
            Gm[a][9 + b] = (a == b) ? 1.0 : 0.0;
        }
        __syncthreads();

        for (int p = 0; p < KK; p++) {
            if (tid == 0) piv = 1.0 / Gm[p][p];
            __syncthreads();
            if (tid < 18) Gm[p][tid] *= piv;
            __syncthreads();
            if (tid < KK) fac[tid] = Gm[tid][p];
            __syncthreads();
            if (tid < 162) {
                int r = tid / 18, c = tid % 18;
                if (r != p) Gm[r][c] -= fac[r] * Gm[p][c];
            }
            __syncthreads();
        }

        if (tid < KK2)
            g_Gi[tid] = (float)Gm[tid / KK][9 + tid % KK];
    } else {
        // Wc[j][c][f] = sum_o Ww[c,o,kw]*Wh[o,f,kh]
        __shared__ float sww[CC*(OO+1)];
        __shared__ float swh[OO*OO];
        int j  = blockIdx.x - 1;
        int kh = j / KK, kw = j % KK;

        for (int i = tid; i < CC*OO; i += 256) {
            int c = i >> 6, o = i & 63;
            sww[c*(OO+1) + o] = Ww[(c*OO + o)*KK + kw];
            swh[i]            = Wh[i*KK + kh];
        }
        __syncthreads();

        int f  = tid & 63;
        int c0 = (tid >> 6) * 16;
        float acc[16];
        #pragma unroll
        for (int i = 0; i < 16; i++) acc[i] = 0.0f;
        for (int o = 0; o < OO; o++) {
            float wh = swh[o*OO + f];
            #pragma unroll
            for (int i = 0; i < 16; i++)
                acc[i] += sww[(c0 + i)*(OO+1) + o] * wh;
        }
        float* wcj = g_wc + (size_t)j * CC * OO;
        #pragma unroll
        for (int i = 0; i < 16; i++)
            wcj[(c0 + i)*OO + f] = acc[i];
    }
}

// ---------------------------------------------------------------------------
// K1: per (b,c) image -> ch[j][bc]. float4 LDG + h-recurrence, no Tp LDS.
// 128 threads: thread = (h-slice s = tid>>5 of 32 rows, 4 w-cols w4=(tid&31)*4)
// ---------------------------------------------------------------------------
__global__ __launch_bounds__(128) void k1_analysis(const float* __restrict__ x) {
    __shared__ __align__(16) float red[4*KK*132];  // [s][a][w] padded
    __shared__ float xs[HH];            // xn abscissae
    __shared__ float tew[HH*KK];        // T[w][b] for width analysis tail
    __shared__ float Ms[KK2];
    __shared__ float tmp[KK2];
    __shared__ float gi[KK2];

    int tid = threadIdx.x;
    int bc  = blockIdx.x;
    int s   = tid >> 5;
    int w4  = (tid & 31) * 4;

    if (tid < HH) xs[tid] = g_xn[tid];
    for (int i = tid; i < HH*KK; i += 128) tew[i] = g_Te[i];
    if (tid < KK2) gi[tid] = g_Gi[tid];
    __syncthreads();

    const float* xg = x + (size_t)bc * IMG + w4 + (s * 32) * WW;

    float acc[KK][4];
    #pragma unroll
    for (int k = 0; k < KK; k++)
        #pragma unroll
        for (int i = 0; i < 4; i++) acc[k][i] = 0.0f;

    #pragma unroll 4
    for (int hh = 0; hh < 32; hh++) {
        float4 xv = *(const float4*)(xg + hh*WW);
        float xn = xs[s*32 + hh];
        float x2 = xn + xn;
        // T_0 = 1
        acc[0][0] += xv.x; acc[0][1] += xv.y; acc[0][2] += xv.z; acc[0][3] += xv.w;
        float t0 = 1.0f, t1 = xn;
        acc[1][0] += t1*xv.x; acc[1][1] += t1*xv.y; acc[1][2] += t1*xv.z; acc[1][3] += t1*xv.w;
        #pragma unroll
        for (int k = 2; k < KK; k++) {
            float t2 = x2*t1 - t0;
            acc[k][0] += t2*xv.x; acc[k][1] += t2*xv.y;
            acc[k][2] += t2*xv.z; acc[k][3] += t2*xv.w;
            t0 = t1; t1 = t2;
        }
    }

    // partials -> smem: red[s][a][w]
    #pragma unroll
    for (int k = 0; k < KK; k++)
        *(float4*)(red + (s*KK + k)*132 + w4) =
            make_float4(acc[k][0], acc[k][1], acc[k][2], acc[k][3]);
    __syncthreads();

    // reduce slices: red[0][a][w] = sum_s
    {
        int w = tid;                    // 128 threads = 128 w
        #pragma unroll
        for (int k = 0; k < KK; k++) {
            float v = red[(0*KK + k)*132 + w] + red[(1*KK + k)*132 + w]
                    + red[(2*KK + k)*132 + w] + red[(3*KK + k)*132 + w];
            red[k*132 + w] = v;
        }
    }
    __syncthreads();

    // width analysis: M[a][b] = sum_w red[a][w] * T[w][b]
    if (tid < KK2) {
        int a = tid / KK, b = tid % KK;
        float sum = 0.0f;
        #pragma unroll 4
        for (int w = 0; w < WW; w++)
            sum += red[a*132 + w] * tew[w*KK + b];
        Ms[tid] = sum;
    }
    __syncthreads();

    // ch = Ginv * M * Ginv^T
    if (tid < KK2) {
        int kh = tid / KK, b = tid % KK;
        float sum = 0.0f;
        #pragma unroll
        for (int a = 0; a < KK; a++)
            sum += gi[kh*KK + a] * Ms[a*KK + b];
        tmp[tid] = sum;
    }
    __syncthreads();
    if (tid < KK2) {
        int kh = tid / KK, kw = tid % KK;
        float sum = 0.0f;
        #pragma unroll
        for (int b = 0; b < KK; b++)
            sum += tmp[kh*KK + b] * gi[kw*KK + b];
        g_ch[(size_t)tid * BC + bc] = sum;
    }
}

// ---------------------------------------------------------------------------
// K_mix: e[b,f,j] = sum_c ch[j][b,c] * Wc[j][c][f].
// grid = 81 j * 4 b-groups (8 b each); 256 threads: (f, 4 b-pairs)
// ---------------------------------------------------------------------------
__global__ __launch_bounds__(256) void k_mix() {
    __shared__ float chs[8*CC];        // [bl][c]
    __shared__ float wcs[CC*OO];       // [c][f]
    int tid = threadIdx.x;
    int j   = blockIdx.x >> 2;
    int b0  = (blockIdx.x & 3) * 8;

    for (int i = tid; i < 8*CC; i += 256)
        chs[i] = g_ch[(size_t)j * BC + b0*CC + i];
    for (int i = tid; i < CC*OO; i += 256)
        wcs[i] = g_wc[(size_t)j * CC * OO + i];
    __syncthreads();

    int f  = tid & 63;
    int bl = (tid >> 6) * 2;
    float a0 = 0.0f, a1 = 0.0f;
    #pragma unroll 8
    for (int c = 0; c < CC; c++) {
        float wv = wcs[c*OO + f];
        a0 += chs[bl*CC + c]     * wv;
        a1 += chs[(bl+1)*CC + c] * wv;
    }
    g_e[(size_t)((b0 + bl    )*OO + f) * KK2 + j] = a0;
    g_e[(size_t)((b0 + bl + 1)*OO + f) * KK2 + j] = a1;
}

// ---------------------------------------------------------------------------
// K4: out[b,f,h,w] = sum_kh T[h,kh] * v[kh][w],  v[kh][w] = sum_kw e*T[w,kw]
// one block per (b,f); 256 threads = (4 w's, 16 h's); Te via recurrence.
// ---------------------------------------------------------------------------
__global__ __launch_bounds__(256) void k4_synth(float* __restrict__ out) {
    __shared__ __align__(16) float vs[KK*132];     // [kh][w] padded
    __shared__ float es[KK2];
    __shared__ float xs[HH];
    int tid = threadIdx.x;
    int bf  = blockIdx.x;

    if (tid < KK2) es[tid] = g_e[(size_t)bf * KK2 + tid];
    if (tid >= 128 && tid < 256) xs[tid-128] = g_xn[tid-128];
    __syncthreads();

    // v[kh][w] via width recurrence (threads 0..127)
    if (tid < 128) {
        int w = tid;
        float xn = xs[w], x2 = xn + xn;
        float tw[KK];
        tw[0] = 1.0f; tw[1] = xn;
        #pragma unroll
        for (int k = 2; k < KK; k++) tw[k] = x2*tw[k-1] - tw[k-2];
        #pragma unroll
        for (int kh = 0; kh < KK; kh++) {
            float s = 0.0f;
            #pragma unroll
            for (int kw = 0; kw < KK; kw++) s += es[kh*KK + kw] * tw[kw];
            vs[kh*132 + w] = s;
        }
    }
    __syncthreads();

    int w4 = (tid & 31) * 4;
    int h0 = (tid >> 5) * 16;
    float4 vr[KK];
    #pragma unroll
    for (int k = 0; k < KK; k++) vr[k] = *(const float4*)(vs + k*132 + w4);

    float* op = out + (size_t)bf * IMG + w4;
    #pragma unroll 2
    for (int hh = 0; hh < 16; hh++) {
        int h = h0 + hh;
        float xn = xs[h], x2 = xn + xn;
        float4 o;
        o.x = vr[0].x; o.y = vr[0].y; o.z = vr[0].z; o.w = vr[0].w;
        float t0 = 1.0f, t1 = xn;
        o.x += t1*vr[1].x; o.y += t1*vr[1].y; o.z += t1*vr[1].z; o.w += t1*vr[1].w;
        #pragma unroll
        for (int k = 2; k < KK; k++) {
            float t2 = x2*t1 - t0;
            o.x += t2*vr[k].x; o.y += t2*vr[k].y;
            o.z += t2*vr[k].z; o.w += t2*vr[k].w;
            t0 = t1; t1 = t2;
        }
        *(float4*)(op + h*WW) = o;
    }
}

// ---------------------------------------------------------------------------
extern "C" void kernel_launch(void* const* d_in, const int* in_sizes, int n_in,
                              void* d_out, int out_size) {
    const float* x  = (const float*)d_in[0];
    const float* Ww = (const float*)d_in[1];
    const float* Wh = (const float*)d_in[2];
    float* out = (float*)d_out;

    kA_setup_wc<<<1 + KK2, 256>>>(Ww, Wh);
    k1_analysis<<<BC, 128>>>(x);
    k_mix<<<KK2*4, 256>>>();
    k4_synth<<<BF, 256>>>(out);
}

// round 6
// speedup vs baseline: 4.0495x; 1.0336x over previous
#include <cuda_runtime.h>
#include <math.h>

// ---------------------------------------------------------------------------
// ChebConv2D  (B=32, C=64, H=W=128, O=64, K=9)
//
//   M [b,c,a,bb]  = sum_h sum_w T[h,a] x[b,c,h,w] T[w,bb]   (k1, recurrence+parity)
//   ch[b,c,kh,kw] = Ginv M Ginv^T                           (k1 tail)
//   Wc[kh,kw,c,f] = sum_o W_w[c,o,kw] * W_h[o,f,kh]         (setup)
//   e [b,f,kh,kw] = sum_c ch[b,c,kh,kw] * Wc[kh,kw,c,f]     (k_mix)
//   out[b,f,h,w]  = Te * e * Te^T                           (k4, recurrence+parity)
//
// Parity: T_k(-x) = (-1)^k T_k(x) and xn[127-i] = -xn[i] (symmetric grid)
// halves the per-pixel Chebyshev FMA work in both k1 and k4.
// ---------------------------------------------------------------------------

#define BB   32
#define CC   64
#define HH   128
#define WW   128
#define OO   64
#define KK   9
#define KK2  81
#define BC   (BB*CC)     // 2048
#define BF   (BB*OO)     // 2048
#define IMG  (HH*WW)     // 16384

__device__ float g_Te[HH*KK];        // T[i][k], i*9+k
__device__ float g_Gi[KK2];          // Ginv[kh][a]
__device__ float g_xn[HH];           // clamped chebyshev abscissae
__device__ float g_ch[KK2*BC];       // [j][b*64+c]
__device__ float g_wc[KK2*CC*OO];    // [j][c][f]
__device__ float g_e [BF*KK2];       // [b*64+f][j]

// ---------------------------------------------------------------------------
// kA: block 0 = Chebyshev setup; blocks 1..81 = combined weight Wc[j][c][f]
// ---------------------------------------------------------------------------
__global__ __launch_bounds__(256) void kA_setup_wc(const float* __restrict__ Ww,
                                                   const float* __restrict__ Wh) {
    int tid = threadIdx.x;

    if (blockIdx.x == 0) {
        __shared__ double Td[HH*KK];      // T[i][k]
        __shared__ double Gm[KK][19];     // augmented [G | I]
        __shared__ double piv;
        __shared__ double fac[KK];

        if (tid < HH) {
            double xd = (double)tid / 127.0;
            float  xf = (float)xd;
            float  xn = 2.0f * xf - 1.0f;
            xn = fminf(fmaxf(xn, -1.0f + 1e-6f), 1.0f - 1e-6f);
            g_xn[tid] = xn;
            double x2 = (double)xn;
            double t0 = 1.0, t1 = x2;
            Td[tid*KK + 0] = t0;  g_Te[tid*KK + 0] = 1.0f;
            Td[tid*KK + 1] = t1;  g_Te[tid*KK + 1] = (float)t1;
            #pragma unroll
            for (int k = 2; k < KK; k++) {
                double t2 = 2.0 * x2 * t1 - t0;
                Td[tid*KK + k] = t2;
                g_Te[tid*KK + k] = (float)t2;
                t0 = t1; t1 = t2;
            }
        }
        __syncthreads();

        if (tid < KK2) {
            int a = tid / KK, b = tid % KK;
            double s = 0.0;
            for (int j = 0; j < HH; j++) s += Td[j*KK + a] * Td[j*KK + b];
            Gm[a][b]     = s;
            Gm[a][9 + b] = (a == b) ? 1.0 : 0.0;
        }
        __syncthreads();

        for (int p = 0; p < KK; p++) {
            if (tid == 0) piv = 1.0 / Gm[p][p];
            __syncthreads();
            if (tid < 18) Gm[p][tid] *= piv;
            __syncthreads();
            if (tid < KK) fac[tid] = Gm[tid][p];
            __syncthreads();
            if (tid < 162) {
                int r = tid / 18, c = tid % 18;
                if (r != p) Gm[r][c] -= fac[r] * Gm[p][c];
            }
            __syncthreads();
        }

        if (tid < KK2)
            g_Gi[tid] = (float)Gm[tid / KK][9 + tid % KK];
    } else {
        // Wc[j][c][f] = sum_o Ww[c,o,kw]*Wh[o,f,kh]
        __shared__ float sww[CC*(OO+1)];
        __shared__ float swh[OO*OO];
        int j  = blockIdx.x - 1;
        int kh = j / KK, kw = j % KK;

        for (int i = tid; i < CC*OO; i += 256) {
            int c = i >> 6, o = i & 63;
            sww[c*(OO+1) + o] = Ww[(c*OO + o)*KK + kw];
            swh[i]            = Wh[i*KK + kh];
        }
        __syncthreads();

        int f  = tid & 63;
        int c0 = (tid >> 6) * 16;
        float acc[16];
        #pragma unroll
        for (int i = 0; i < 16; i++) acc[i] = 0.0f;
        for (int o = 0; o < OO; o++) {
            float wh = swh[o*OO + f];
            #pragma unroll
            for (int i = 0; i < 16; i++)
                acc[i] += sww[(c0 + i)*(OO+1) + o] * wh;
        }
        float* wcj = g_wc + (size_t)j * CC * OO;
        #pragma unroll
        for (int i = 0; i < 16; i++)
            wcj[(c0 + i)*OO + f] = acc[i];
    }
}

// ---------------------------------------------------------------------------
// K1: per (b,c) image -> ch[j][bc]. float4 LDG + h-recurrence + parity fold.
// 128 threads: thread = (pair-slice s = tid>>5 of 16 h-pairs, 4 w-cols)
// ---------------------------------------------------------------------------
__global__ __launch_bounds__(128) void k1_analysis(const float* __restrict__ x) {
    __shared__ __align__(16) float red[4*KK*132];  // [s][a][w] padded
    __shared__ float xs[HH];            // xn abscissae
    __shared__ float tew[HH*KK];        // T[w][b] for width-analysis tail
    __shared__ float Ms[KK2];
    __shared__ float tmp[KK2];
    __shared__ float gi[KK2];

    int tid = threadIdx.x;
    int bc  = blockIdx.x;
    int s   = tid >> 5;                 // 0..3 -> h pairs [s*16, s*16+16)
    int w4  = (tid & 31) * 4;

    if (tid < HH) xs[tid] = g_xn[tid];
    for (int i = tid; i < HH*KK; i += 128) tew[i] = g_Te[i];
    if (tid < KK2) gi[tid] = g_Gi[tid];
    __syncthreads();

    const float* xg = x + (size_t)bc * IMG + w4;

    float acc[KK][4];
    #pragma unroll
    for (int k = 0; k < KK; k++)
        #pragma unroll
        for (int i = 0; i < 4; i++) acc[k][i] = 0.0f;

    #pragma unroll 4
    for (int pp = 0; pp < 16; pp++) {
        int h = s*16 + pp;              // lo row; hi row = 127-h
        float4 lo = *(const float4*)(xg + h*WW);
        float4 hi = *(const float4*)(xg + (127-h)*WW);
        float sx = lo.x + hi.x, sy = lo.y + hi.y, sz = lo.z + hi.z, sw = lo.w + hi.w;
        float dx = lo.x - hi.x, dy = lo.y - hi.y, dz = lo.z - hi.z, dw = lo.w - hi.w;
        float xn = xs[h], x2 = xn + xn;
        // k=0 (even): T0=1
        acc[0][0] += sx; acc[0][1] += sy; acc[0][2] += sz; acc[0][3] += sw;
        // k=1 (odd): T1=xn
        float t0 = 1.0f, t1 = xn;
        acc[1][0] += t1*dx; acc[1][1] += t1*dy; acc[1][2] += t1*dz; acc[1][3] += t1*dw;
        #pragma unroll
        for (int k = 2; k < KK; k++) {
            float t2 = x2*t1 - t0;
            if ((k & 1) == 0) {
                acc[k][0] += t2*sx; acc[k][1] += t2*sy;
                acc[k][2] += t2*sz; acc[k][3] += t2*sw;
            } else {
                acc[k][0] += t2*dx; acc[k][1] += t2*dy;
                acc[k][2] += t2*dz; acc[k][3] += t2*dw;
            }
            t0 = t1; t1 = t2;
        }
    }

    // partials -> smem: red[s][a][w]
    #pragma unroll
    for (int k = 0; k < KK; k++)
        *(float4*)(red + (s*KK + k)*132 + w4) =
            make_float4(acc[k][0], acc[k][1], acc[k][2], acc[k][3]);
    __syncthreads();

    // reduce slices: red[0][a][w] = sum_s
    {
        int w = tid;                    // 128 threads = 128 w
        #pragma unroll
        for (int k = 0; k < KK; k++) {
            float v = red[(0*KK + k)*132 + w] + red[(1*KK + k)*132 + w]
                    + red[(2*KK + k)*132 + w] + red[(3*KK + k)*132 + w];
            red[k*132 + w] = v;
        }
    }
    __syncthreads();

    // width analysis: M[a][b] = sum_w red[a][w] * T[w][b]
    if (tid < KK2) {
        int a = tid / KK, b = tid % KK;
        float sum = 0.0f;
        #pragma unroll 4
        for (int w = 0; w < WW; w++)
            sum += red[a*132 + w] * tew[w*KK + b];
        Ms[tid] = sum;
    }
    __syncthreads();

    // ch = Ginv * M * Ginv^T
    if (tid < KK2) {
        int kh = tid / KK, b = tid % KK;
        float sum = 0.0f;
        #pragma unroll
        for (int a = 0; a < KK; a++)
            sum += gi[kh*KK + a] * Ms[a*KK + b];
        tmp[tid] = sum;
    }
    __syncthreads();
    if (tid < KK2) {
        int kh = tid / KK, kw = tid % KK;
        float sum = 0.0f;
        #pragma unroll
        for (int b = 0; b < KK; b++)
            sum += tmp[kh*KK + b] * gi[kw*KK + b];
        g_ch[(size_t)tid * BC + bc] = sum;
    }
}

// ---------------------------------------------------------------------------
// K_mix: e[b,f,j] = sum_c ch[j][b,c] * Wc[j][c][f].
// grid = 81 j * 4 b-groups (8 b each); 256 threads: (f, 4 b-pairs)
// ---------------------------------------------------------------------------
__global__ __launch_bounds__(256) void k_mix() {
    __shared__ float chs[8*CC];        // [bl][c]
    __shared__ float wcs[CC*OO];       // [c][f]
    int tid = threadIdx.x;
    int j   = blockIdx.x >> 2;
    int b0  = (blockIdx.x & 3) * 8;

    for (int i = tid; i < 8*CC; i += 256)
        chs[i] = g_ch[(size_t)j * BC + b0*CC + i];
    for (int i = tid; i < CC*OO; i += 256)
        wcs[i] = g_wc[(size_t)j * CC * OO + i];
    __syncthreads();

    int f  = tid & 63;
    int bl = (tid >> 6) * 2;
    float a0 = 0.0f, a1 = 0.0f;
    #pragma unroll 8
    for (int c = 0; c < CC; c++) {
        float wv = wcs[c*OO + f];
        a0 += chs[bl*CC + c]     * wv;
        a1 += chs[(bl+1)*CC + c] * wv;
    }
    g_e[(size_t)((b0 + bl    )*OO + f) * KK2 + j] = a0;
    g_e[(size_t)((b0 + bl + 1)*OO + f) * KK2 + j] = a1;
}

// ---------------------------------------------------------------------------
// K4: out = Te * e * Te^T with parity on h.
// one block per (b,f); 256 threads = (4 w's, 8 h-pairs); float4 stores.
// ---------------------------------------------------------------------------
__global__ __launch_bounds__(256) void k4_synth(float* __restrict__ out) {
    __shared__ __align__(16) float vs[KK*132];     // [kh][w] padded
    __shared__ float es[KK2];
    __shared__ float xs[HH];
    int tid = threadIdx.x;
    int bf  = blockIdx.x;

    if (tid < KK2) es[tid] = g_e[(size_t)bf * KK2 + tid];
    if (tid >= 128 && tid < 256) xs[tid-128] = g_xn[tid-128];
    __syncthreads();

    // v[kh][w] via width recurrence (threads 0..127)
    if (tid < 128) {
        int w = tid;
        float xn = xs[w], x2 = xn + xn;
        float tw[KK];
        tw[0] = 1.0f; tw[1] = xn;
        #pragma unroll
        for (int k = 2; k < KK; k++) tw[k] = x2*tw[k-1] - tw[k-2];
        #pragma unroll
        for (int kh = 0; kh < KK; kh++) {
            float sv = 0.0f;
            #pragma unroll
            for (int kw = 0; kw < KK; kw++) sv += es[kh*KK + kw] * tw[kw];
            vs[kh*132 + w] = sv;
        }
    }
    __syncthreads();

    int w4 = (tid & 31) * 4;
    int s  = tid >> 5;                  // 0..7 -> h pairs [s*8, s*8+8)
    float4 vr[KK];
    #pragma unroll
    for (int k = 0; k < KK; k++) vr[k] = *(const float4*)(vs + k*132 + w4);

    float* op = out + (size_t)bf * IMG + w4;
    #pragma unroll 2
    for (int pp = 0; pp < 8; pp++) {
        int h = s*8 + pp;               // lo row; hi = 127-h
        float xn = xs[h], x2 = xn + xn;
        float4 E, O;
        E.x = vr[0].x; E.y = vr[0].y; E.z = vr[0].z; E.w = vr[0].w;
        float t0 = 1.0f, t1 = xn;
        O.x = t1*vr[1].x; O.y = t1*vr[1].y; O.z = t1*vr[1].z; O.w = t1*vr[1].w;
        #pragma unroll
        for (int k = 2; k < KK; k++) {
            float t2 = x2*t1 - t0;
            if ((k & 1) == 0) {
                E.x += t2*vr[k].x; E.y += t2*vr[k].y;
                E.z += t2*vr[k].z; E.w += t2*vr[k].w;
            } else {
                O.x += t2*vr[k].x; O.y += t2*vr[k].y;
                O.z += t2*vr[k].z; O.w += t2*vr[k].w;
            }
            t0 = t1; t1 = t2;
        }
        float4 lo, hi;
        lo.x = E.x + O.x; lo.y = E.y + O.y; lo.z = E.z + O.z; lo.w = E.w + O.w;
        hi.x = E.x - O.x; hi.y = E.y - O.y; hi.z = E.z - O.z; hi.w = E.w - O.w;
        *(float4*)(op + h*WW)       = lo;
        *(float4*)(op + (127-h)*WW) = hi;
    }
}

// ---------------------------------------------------------------------------
extern "C" void kernel_launch(void* const* d_in, const int* in_sizes, int n_in,
                              void* d_out, int out_size) {
    const float* x  = (const float*)d_in[0];
    const float* Ww = (const float*)d_in[1];
    const float* Wh = (const float*)d_in[2];
    float* out = (float*)d_out;

    kA_setup_wc<<<1 + KK2, 256>>>(Ww, Wh);
    k1_analysis<<<BC, 128>>>(x);
    k_mix<<<KK2*4, 256>>>();
    k4_synth<<<BF, 256>>>(out);
}

// round 7
// speedup vs baseline: 4.0682x; 1.0046x over previous
#include <cuda_runtime.h>
#include <math.h>

// ---------------------------------------------------------------------------
// ChebConv2D  (B=32, C=64, H=W=128, O=64, K=9)
//
//   M [b,c,a,bb]  = sum_h sum_w T[h,a] x[b,c,h,w] T[w,bb]   (k1, recurrence+parity)
//   ch[b,c,kh,kw] = Ginv M Ginv^T                           (k1 tail)
//   Wc[kh,kw,c,f] = sum_o W_w[c,o,kw] * W_h[o,f,kh]         (setup)
//   e [b,f,kh,kw] = sum_c ch[b,c,kh,kw] * Wc[kh,kw,c,f]     (k_mix)
//   out[b,f,h,w]  = Te * e * Te^T                           (k4, recurrence+parity)
//
// Parity: T_k(-x) = (-1)^k T_k(x), xn[127-i] = -xn[i].
// ---------------------------------------------------------------------------

#define BB   32
#define CC   64
#define HH   128
#define WW   128
#define OO   64
#define KK   9
#define KK2  81
#define BC   (BB*CC)     // 2048
#define BF   (BB*OO)     // 2048
#define IMG  (HH*WW)     // 16384

__device__ float g_Te[HH*KK];        // T[i][k], i*9+k
__device__ float g_Gi[KK2];          // Ginv[kh][a]
__device__ float g_xn[HH];           // clamped chebyshev abscissae
__device__ float g_ch[KK2*BC];       // [j][b*64+c]
__device__ float g_wc[KK2*CC*OO];    // [j][c][f]
__device__ float g_e [BF*KK2];       // [b*64+f][j]

// ---------------------------------------------------------------------------
// kA: block 0 = Chebyshev setup (fp32, warp-level GJ);
//     blocks 1..81 = combined weight Wc[j][c][f]
// ---------------------------------------------------------------------------
__global__ __launch_bounds__(256) void kA_setup_wc(const float* __restrict__ Ww,
                                                   const float* __restrict__ Wh) {
    int tid = threadIdx.x;

    if (blockIdx.x == 0) {
        __shared__ float Tf[HH*KK];       // T[i][k]
        __shared__ float Gm[KK][19];      // augmented [G | I]

        if (tid < HH) {
            double xd = (double)tid / 127.0;
            float  xf = (float)xd;
            float  xn = 2.0f * xf - 1.0f;
            xn = fminf(fmaxf(xn, -1.0f + 1e-6f), 1.0f - 1e-6f);
            g_xn[tid] = xn;
            float x2 = xn + xn;
            float t0 = 1.0f, t1 = xn;
            Tf[tid*KK + 0] = 1.0f;  g_Te[tid*KK + 0] = 1.0f;
            Tf[tid*KK + 1] = t1;    g_Te[tid*KK + 1] = t1;
            #pragma unroll
            for (int k = 2; k < KK; k++) {
                float t2 = x2*t1 - t0;
                Tf[tid*KK + k] = t2;
                g_Te[tid*KK + k] = t2;
                t0 = t1; t1 = t2;
            }
        }
        __syncthreads();

        if (tid < KK2) {
            int a = tid / KK, b = tid % KK;
            float s0 = 0.f, s1 = 0.f, s2 = 0.f, s3 = 0.f;
            #pragma unroll 4
            for (int j = 0; j < HH; j += 4) {
                s0 += Tf[(j+0)*KK + a] * Tf[(j+0)*KK + b];
                s1 += Tf[(j+1)*KK + a] * Tf[(j+1)*KK + b];
                s2 += Tf[(j+2)*KK + a] * Tf[(j+2)*KK + b];
                s3 += Tf[(j+3)*KK + a] * Tf[(j+3)*KK + b];
            }
            Gm[a][b]     = (s0+s1) + (s2+s3);
            Gm[a][9 + b] = (a == b) ? 1.0f : 0.0f;
        }
        __syncthreads();

        if (tid < 32) {                   // warp-level Gauss-Jordan
            int lane = tid;
            for (int p = 0; p < KK; p++) {
                float pv = Gm[p][p];
                __syncwarp();
                if (lane < 18) Gm[p][lane] /= pv;
                __syncwarp();
                float fac[KK];
                #pragma unroll
                for (int r = 0; r < KK; r++) fac[r] = Gm[r][p];
                __syncwarp();
                if (lane < 18) {
                    #pragma unroll
                    for (int r = 0; r < KK; r++)
                        if (r != p) Gm[r][lane] -= fac[r] * Gm[p][lane];
                }
                __syncwarp();
            }
        }
        __syncthreads();

        if (tid < KK2)
            g_Gi[tid] = Gm[tid / KK][9 + tid % KK];
    } else {
        // Wc[j][c][f] = sum_o Ww[c,o,kw]*Wh[o,f,kh]
        __shared__ float sww[CC*(OO+1)];
        __shared__ float swh[OO*OO];
        int j  = blockIdx.x - 1;
        int kh = j / KK, kw = j % KK;

        for (int i = tid; i < CC*OO; i += 256) {
            int c = i >> 6, o = i & 63;
            sww[c*(OO+1) + o] = Ww[(c*OO + o)*KK + kw];
            swh[i]            = Wh[i*KK + kh];
        }
        __syncthreads();

        int f  = tid & 63;
        int c0 = (tid >> 6) * 16;
        float acc[16];
        #pragma unroll
        for (int i = 0; i < 16; i++) acc[i] = 0.0f;
        for (int o = 0; o < OO; o++) {
            float wh = swh[o*OO + f];
            #pragma unroll
            for (int i = 0; i < 16; i++)
                acc[i] += sww[(c0 + i)*(OO+1) + o] * wh;
        }
        float* wcj = g_wc + (size_t)j * CC * OO;
        #pragma unroll
        for (int i = 0; i < 16; i++)
            wcj[(c0 + i)*OO + f] = acc[i];
    }
}

// ---------------------------------------------------------------------------
// K1: per (b,c) image -> ch[j][bc]. float4 LDG + h-recurrence + parity fold.
// 128 threads: thread = (pair-slice s = tid>>5 of 16 h-pairs, 4 w-cols)
// ---------------------------------------------------------------------------
__global__ __launch_bounds__(128) void k1_analysis(const float* __restrict__ x) {
    __shared__ __align__(16) float red[4*KK*132];  // [s][a][w] padded
    __shared__ float xs[HH];            // xn abscissae
    __shared__ float tew[HH*KK];        // T[w][b] for width-analysis tail
    __shared__ float Ms[KK2];
    __shared__ float tmp[KK2];
    __shared__ float gi[KK2];

    int tid = threadIdx.x;
    int bc  = blockIdx.x;
    int s   = tid >> 5;                 // 0..3 -> h pairs [s*16, s*16+16)
    int w4  = (tid & 31) * 4;

    if (tid < HH) xs[tid] = g_xn[tid];
    for (int i = tid; i < HH*KK; i += 128) tew[i] = g_Te[i];
    if (tid < KK2) gi[tid] = g_Gi[tid];
    __syncthreads();

    const float* xg = x + (size_t)bc * IMG + w4;

    float acc[KK][4];
    #pragma unroll
    for (int k = 0; k < KK; k++)
        #pragma unroll
        for (int i = 0; i < 4; i++) acc[k][i] = 0.0f;

    #pragma unroll 4
    for (int pp = 0; pp < 16; pp++) {
        int h = s*16 + pp;              // lo row; hi row = 127-h
        float4 lo = *(const float4*)(xg + h*WW);
        float4 hi = *(const float4*)(xg + (127-h)*WW);
        float sx = lo.x + hi.x, sy = lo.y + hi.y, sz = lo.z + hi.z, sw = lo.w + hi.w;
        float dx = lo.x - hi.x, dy = lo.y - hi.y, dz = lo.z - hi.z, dw = lo.w - hi.w;
        float xn = xs[h], x2 = xn + xn;
        acc[0][0] += sx; acc[0][1] += sy; acc[0][2] += sz; acc[0][3] += sw;
        float t0 = 1.0f, t1 = xn;
        acc[1][0] += t1*dx; acc[1][1] += t1*dy; acc[1][2] += t1*dz; acc[1][3] += t1*dw;
        #pragma unroll
        for (int k = 2; k < KK; k++) {
            float t2 = x2*t1 - t0;
            if ((k & 1) == 0) {
                acc[k][0] += t2*sx; acc[k][1] += t2*sy;
                acc[k][2] += t2*sz; acc[k][3] += t2*sw;
            } else {
                acc[k][0] += t2*dx; acc[k][1] += t2*dy;
                acc[k][2] += t2*dz; acc[k][3] += t2*dw;
            }
            t0 = t1; t1 = t2;
        }
    }

    // partials -> smem: red[s][a][w]
    #pragma unroll
    for (int k = 0; k < KK; k++)
        *(float4*)(red + (s*KK + k)*132 + w4) =
            make_float4(acc[k][0], acc[k][1], acc[k][2], acc[k][3]);
    __syncthreads();

    // reduce slices: red[0][a][w] = sum_s
    {
        int w = tid;
        #pragma unroll
        for (int k = 0; k < KK; k++) {
            float v = red[(0*KK + k)*132 + w] + red[(1*KK + k)*132 + w]
                    + red[(2*KK + k)*132 + w] + red[(3*KK + k)*132 + w];
            red[k*132 + w] = v;
        }
    }
    __syncthreads();

    // width analysis with w-parity: M[a][b] = sum_{w<64} (red[w] +- red[127-w]) T[w][b]
    if (tid < KK2) {
        int a = tid / KK, b = tid % KK;
        float sgn = (b & 1) ? -1.0f : 1.0f;
        float sum = 0.0f;
        #pragma unroll 4
        for (int w = 0; w < 64; w++) {
            float v = red[a*132 + w] + sgn * red[a*132 + 127 - w];
            sum += v * tew[w*KK + b];
        }
        Ms[tid] = sum;
    }
    __syncthreads();

    // ch = Ginv * M * Ginv^T
    if (tid < KK2) {
        int kh = tid / KK, b = tid % KK;
        float sum = 0.0f;
        #pragma unroll
        for (int a = 0; a < KK; a++)
            sum += gi[kh*KK + a] * Ms[a*KK + b];
        tmp[tid] = sum;
    }
    __syncthreads();
    if (tid < KK2) {
        int kh = tid / KK, kw = tid % KK;
        float sum = 0.0f;
        #pragma unroll
        for (int b = 0; b < KK; b++)
            sum += tmp[kh*KK + b] * gi[kw*KK + b];
        g_ch[(size_t)tid * BC + bc] = sum;
    }
}

// ---------------------------------------------------------------------------
// K_mix: e[b,f,j] = sum_c ch[j][b,c] * Wc[j][c][f].
// grid = 81 j * 4 b-groups (8 b each); 256 threads: (f, 4 b-pairs)
// ---------------------------------------------------------------------------
__global__ __launch_bounds__(256) void k_mix() {
    __shared__ float chs[8*CC];        // [bl][c]
    __shared__ float wcs[CC*OO];       // [c][f]
    int tid = threadIdx.x;
    int j   = blockIdx.x >> 2;
    int b0  = (blockIdx.x & 3) * 8;

    for (int i = tid; i < 8*CC; i += 256)
        chs[i] = g_ch[(size_t)j * BC + b0*CC + i];
    for (int i = tid; i < CC*OO; i += 256)
        wcs[i] = g_wc[(size_t)j * CC * OO + i];
    __syncthreads();

    int f  = tid & 63;
    int bl = (tid >> 6) * 2;
    float a0 = 0.0f, a1 = 0.0f;
    #pragma unroll 8
    for (int c = 0; c < CC; c++) {
        float wv = wcs[c*OO + f];
        a0 += chs[bl*CC + c]     * wv;
        a1 += chs[(bl+1)*CC + c] * wv;
    }
    g_e[(size_t)((b0 + bl    )*OO + f) * KK2 + j] = a0;
    g_e[(size_t)((b0 + bl + 1)*OO + f) * KK2 + j] = a1;
}

// ---------------------------------------------------------------------------
// K4: out = Te * e * Te^T with parity on h.
// one block per (b,f); 256 threads = (4 w's, 8 h-pairs); float4 stores.
// vs-phase uses all 256 threads (kh split across halves).
// ---------------------------------------------------------------------------
__global__ __launch_bounds__(256) void k4_synth(float* __restrict__ out) {
    __shared__ __align__(16) float vs[KK*132];     // [kh][w] padded
    __shared__ float es[KK2];
    __shared__ float xs[HH];
    int tid = threadIdx.x;
    int bf  = blockIdx.x;

    if (tid < HH) xs[tid] = g_xn[tid];
    if (tid >= 128 && tid < 128 + KK2) es[tid-128] = g_e[(size_t)bf * KK2 + (tid-128)];
    __syncthreads();

    // v[kh][w] via width recurrence; all 256 threads (kh split 0..3 / 4..8)
    {
        int w  = tid & 127;
        int hi = tid >> 7;              // 0: kh 0..3, 1: kh 4..8
        float xn = xs[w], x2 = xn + xn;
        float tw[KK];
        tw[0] = 1.0f; tw[1] = xn;
        #pragma unroll
        for (int k = 2; k < KK; k++) tw[k] = x2*tw[k-1] - tw[k-2];
        int kh0 = hi ? 4 : 0;
        int kh1 = hi ? 9 : 4;
        for (int kh = kh0; kh < kh1; kh++) {
            float sv = 0.0f;
            #pragma unroll
            for (int kw = 0; kw < KK; kw++) sv += es[kh*KK + kw] * tw[kw];
            vs[kh*132 + w] = sv;
        }
    }
    __syncthreads();

    int w4 = (tid & 31) * 4;
    int s  = tid >> 5;                  // 0..7 -> h pairs [s*8, s*8+8)
    float4 vr[KK];
    #pragma unroll
    for (int k = 0; k < KK; k++) vr[k] = *(const float4*)(vs + k*132 + w4);

    float* op = out + (size_t)bf * IMG + w4;
    #pragma unroll 4
    for (int pp = 0; pp < 8; pp++) {
        int h = s*8 + pp;               // lo row; hi = 127-h
        float xn = xs[h], x2 = xn + xn;
        float4 E, O;
        E.x = vr[0].x; E.y = vr[0].y; E.z = vr[0].z; E.w = vr[0].w;
        float t0 = 1.0f, t1 = xn;
        O.x = t1*vr[1].x; O.y = t1*vr[1].y; O.z = t1*vr[1].z; O.w = t1*vr[1].w;
        #pragma unroll
        for (int k = 2; k < KK; k++) {
            float t2 = x2*t1 - t0;
            if ((k & 1) == 0) {
                E.x += t2*vr[k].x; E.y += t2*vr[k].y;
                E.z += t2*vr[k].z; E.w += t2*vr[k].w;
            } else {
                O.x += t2*vr[k].x; O.y += t2*vr[k].y;
                O.z += t2*vr[k].z; O.w += t2*vr[k].w;
            }
            t0 = t1; t1 = t2;
        }
        float4 lo, hi;
        lo.x = E.x + O.x; lo.y = E.y + O.y; lo.z = E.z + O.z; lo.w = E.w + O.w;
        hi.x = E.x - O.x; hi.y = E.y - O.y; hi.z = E.z - O.z; hi.w = E.w - O.w;
        *(float4*)(op + h*WW)       = lo;
        *(float4*)(op + (127-h)*WW) = hi;
    }
}

// ---------------------------------------------------------------------------
extern "C" void kernel_launch(void* const* d_in, const int* in_sizes, int n_in,
                              void* d_out, int out_size) {
    const float* x  = (const float*)d_in[0];
    const float* Ww = (const float*)d_in[1];
    const float* Wh = (const float*)d_in[2];
    float* out = (float*)d_out;

    kA_setup_wc<<<1 + KK2, 256>>>(Ww, Wh);
    k1_analysis<<<BC, 128>>>(x);
    k_mix<<<KK2*4, 256>>>();
    k4_synth<<<BF, 256>>>(out);
}